// round 3
// baseline (speedup 1.0000x reference)
#include <cuda_runtime.h>
#include <cstddef>

#define BB 2
#define TT 2048
#define DD 1024
#define HH 16
#define HD 64

// Scratch (device globals: allocation-free per harness rules)
__device__ float g_q[BB*HH*TT*HD];   // (b,h,t,d)
__device__ float g_k[BB*HH*TT*HD];   // (b,h,t,d)
__device__ float g_v[BB*HH*TT*HD];   // (b,h,t,d)
__device__ float g_y[BB*TT*HH*HD];   // (b,t,h,d)

// exp on the FMA pipe (no MUFU): exp(x) = 2^(x*log2e), degree-5 Taylor of 2^f,
// exponent spliced via int bits. |rel err| ~8e-5, valid for x <= 0 (clamped).
__device__ __forceinline__ float fast_exp(float x) {
    float t = x * 1.4426950408889634f;
    t = fmaxf(t, -126.0f);
    float fi = floorf(t);
    float f = t - fi;
    float p = 1.3333558e-3f;
    p = fmaf(p, f, 9.6181291e-3f);
    p = fmaf(p, f, 5.5504109e-2f);
    p = fmaf(p, f, 2.4022651e-1f);
    p = fmaf(p, f, 6.9314718e-1f);
    p = fmaf(p, f, 1.0f);
    return p * __int_as_float(((int)fi + 127) << 23);
}

// ---------------------------------------------------------------------------
// Kernel 1: qk = x_norm @ qk_w^T + qk_b, scattered into g_q/g_k (b,h,t,d).
// C[M=4096][N=2048], K=1024. 128x128x16 tiles, 256 threads, 8x8 microtile
// (split as 2x2 blocks of 4 for conflict-free float4 smem frags).
// ---------------------------------------------------------------------------
__global__ __launch_bounds__(256, 2)
void qk_proj_kernel(const float* __restrict__ A, const float* __restrict__ W,
                    const float* __restrict__ bias) {
    __shared__ float As[16][128];
    __shared__ float Ws[16][128];
    const int bn = blockIdx.x * 128;
    const int bm = blockIdx.y * 128;
    const int tid = threadIdx.x;
    const int rm = tid >> 4;   // 0..15
    const int cn = tid & 15;   // 0..15

    float acc[8][8];
    #pragma unroll
    for (int i = 0; i < 8; i++)
        #pragma unroll
        for (int j = 0; j < 8; j++) acc[i][j] = 0.f;

    for (int k0 = 0; k0 < DD; k0 += 16) {
        #pragma unroll
        for (int it = 0; it < 2; it++) {
            int idx = tid + it * 256;        // 0..511
            int row = idx & 127;
            int kk  = (idx >> 7) * 4;        // 0,4,8,12
            float4 va = *(const float4*)(A + (size_t)(bm + row) * DD + k0 + kk);
            As[kk+0][row] = va.x; As[kk+1][row] = va.y;
            As[kk+2][row] = va.z; As[kk+3][row] = va.w;
            float4 vw = *(const float4*)(W + (size_t)(bn + row) * DD + k0 + kk);
            Ws[kk+0][row] = vw.x; Ws[kk+1][row] = vw.y;
            Ws[kk+2][row] = vw.z; Ws[kk+3][row] = vw.w;
        }
        __syncthreads();
        #pragma unroll
        for (int kk = 0; kk < 16; kk++) {
            float a[8], w[8];
            *(float4*)&a[0] = *(const float4*)&As[kk][rm * 4];
            *(float4*)&a[4] = *(const float4*)&As[kk][64 + rm * 4];
            *(float4*)&w[0] = *(const float4*)&Ws[kk][cn * 4];
            *(float4*)&w[4] = *(const float4*)&Ws[kk][64 + cn * 4];
            #pragma unroll
            for (int i = 0; i < 8; i++)
                #pragma unroll
                for (int j = 0; j < 8; j++)
                    acc[i][j] = fmaf(a[i], w[j], acc[i][j]);
        }
        __syncthreads();
    }

    // Epilogue: +bias, scatter to q/k in (b,h,t,d) layout. 8-col groups never
    // cross a 64 (head) or 1024 (q/k) boundary since bn,64-blocks align.
    #pragma unroll
    for (int jh = 0; jh < 2; jh++) {
        int n0 = bn + jh * 64 + cn * 4;
        float4 bv = *(const float4*)(bias + n0);
        int nn = n0 & (DD - 1);
        int hh = nn >> 6, dd = nn & 63;
        float* base = (n0 < DD) ? g_q : g_k;
        #pragma unroll
        for (int ih = 0; ih < 2; ih++) {
            #pragma unroll
            for (int i = 0; i < 4; i++) {
                int m = bm + ih * 64 + rm * 4 + i;
                int b = m >> 11, t = m & (TT - 1);
                float4 o;
                o.x = acc[ih*4+i][jh*4+0] + bv.x;
                o.y = acc[ih*4+i][jh*4+1] + bv.y;
                o.z = acc[ih*4+i][jh*4+2] + bv.z;
                o.w = acc[ih*4+i][jh*4+3] + bv.w;
                *(float4*)(base + ((size_t)((b*HH + hh)*TT + t)) * HD + dd) = o;
            }
        }
    }
}

// ---------------------------------------------------------------------------
// Kernel 2/4: head-mix einsum. mode 0: v[b,i,t,d] = sum_j xt[b,t,j,d]*vf[i,j]
// (scatter into g_v). mode 1: out[b,t,i,d] = sum_j g_y[b,t,j,d]*of[i,j]
// (contiguous into d_out). One block per (b,t) row, memory-bound.
// ---------------------------------------------------------------------------
__global__ __launch_bounds__(256)
void mix_kernel(const float* __restrict__ src, const float* __restrict__ fact,
                float* __restrict__ dst, int mode) {
    __shared__ float xs[1024];
    __shared__ float fs[256];
    const int bt = blockIdx.x;         // b*T + t
    const int tid = threadIdx.x;
    const float* s = (mode == 0) ? src : g_y;
    *(float4*)&xs[tid * 4] = *(const float4*)(s + (size_t)bt * 1024 + tid * 4);
    if (tid < 64) *(float4*)&fs[tid * 4] = *(const float4*)(fact + tid * 4);
    __syncthreads();

    const int o = tid * 4;
    const int i = o >> 6, d = o & 63;
    float4 acc = make_float4(0.f, 0.f, 0.f, 0.f);
    #pragma unroll
    for (int j = 0; j < 16; j++) {
        float f = fs[i * 16 + j];
        float4 x = *(const float4*)&xs[j * 64 + d];
        acc.x = fmaf(f, x.x, acc.x); acc.y = fmaf(f, x.y, acc.y);
        acc.z = fmaf(f, x.z, acc.z); acc.w = fmaf(f, x.w, acc.w);
    }
    if (mode == 0) {
        int b = bt >> 11, t = bt & (TT - 1);
        *(float4*)(g_v + ((size_t)(b*HH + i)*TT + t) * HD + d) = acc;
    } else {
        *(float4*)(dst + (size_t)bt * 1024 + o) = acc;
    }
}

// ---------------------------------------------------------------------------
// Kernel 3: causal flash attention with ALiBi, fp32.
// Block = one (b,h) x one 64-row q-tile; each block processes the work-balanced
// pair (qt, 31-qt). 256 threads, 4x4 microtiles for both 64^3 GEMM phases.
// smem: Qs[d][r], KPs (K as [d][c], then P as [c][r] XOR-swizzled), Vs[c][d].
// Exactly 48KB static shared.
// ---------------------------------------------------------------------------
__global__ __launch_bounds__(256)
void attn_kernel() {
    __shared__ float Qs[64][64];
    __shared__ float KPs[64][64];
    __shared__ float Vs[64][64];

    const int bh = blockIdx.y;
    const int h = bh & (HH - 1);
    const float slope = exp2f(-0.5f * (float)(h + 1));   // H=16 pow2 slopes
    const float* Q = g_q + (size_t)bh * TT * HD;
    const float* K = g_k + (size_t)bh * TT * HD;
    const float* V = g_v + (size_t)bh * TT * HD;
    const int tid = threadIdx.x;
    const int tr = tid >> 4;   // row group 0..15 (rows tr*4..tr*4+3)
    const int tc = tid & 15;   // col group 0..15

    for (int rep = 0; rep < 2; rep++) {
        const int qt = rep ? (31 - (int)blockIdx.x) : (int)blockIdx.x;
        __syncthreads();
        // Load Q tile transposed: Qs[d][r]
        #pragma unroll
        for (int it = 0; it < 4; it++) {
            int idx = tid + it * 256;       // 0..1023
            int r = idx >> 4;
            int dd = (idx & 15) * 4;
            float4 v = *(const float4*)(Q + (size_t)(qt*64 + r) * HD + dd);
            Qs[dd+0][r] = v.x; Qs[dd+1][r] = v.y;
            Qs[dd+2][r] = v.z; Qs[dd+3][r] = v.w;
        }

        float O[4][4];
        float m_i[4], l_i[4];
        #pragma unroll
        for (int i = 0; i < 4; i++) {
            m_i[i] = -1e30f; l_i[i] = 0.f;
            #pragma unroll
            for (int j = 0; j < 4; j++) O[i][j] = 0.f;
        }

        for (int kt = 0; kt <= qt; kt++) {
            __syncthreads();   // prev PV reads + Qs load complete
            #pragma unroll
            for (int it = 0; it < 4; it++) {
                int idx = tid + it * 256;
                int c = idx >> 4;
                int dd = (idx & 15) * 4;
                float4 kv = *(const float4*)(K + (size_t)(kt*64 + c) * HD + dd);
                KPs[dd+0][c] = kv.x; KPs[dd+1][c] = kv.y;
                KPs[dd+2][c] = kv.z; KPs[dd+3][c] = kv.w;
                *(float4*)&Vs[c][dd] =
                    *(const float4*)(V + (size_t)(kt*64 + c) * HD + dd);
            }
            __syncthreads();

            // S = Q K^T (4x4 per thread)
            float s[4][4];
            #pragma unroll
            for (int i = 0; i < 4; i++)
                #pragma unroll
                for (int j = 0; j < 4; j++) s[i][j] = 0.f;
            #pragma unroll 8
            for (int k = 0; k < 64; k++) {
                float qv[4], kv[4];
                *(float4*)qv = *(const float4*)&Qs[k][tr * 4];
                *(float4*)kv = *(const float4*)&KPs[k][tc * 4];
                #pragma unroll
                for (int i = 0; i < 4; i++)
                    #pragma unroll
                    for (int j = 0; j < 4; j++)
                        s[i][j] = fmaf(qv[i], kv[j], s[i][j]);
            }

            // scale + ALiBi bias + causal mask (only diagonal tile can mask)
            const bool diag = (kt == qt);
            #pragma unroll
            for (int i = 0; i < 4; i++) {
                int qi = qt * 64 + tr * 4 + i;
                #pragma unroll
                for (int j = 0; j < 4; j++) {
                    int ki = kt * 64 + tc * 4 + j;
                    float v = fmaf(s[i][j], 0.125f, slope * (float)(ki - qi));
                    s[i][j] = (diag && ki > qi) ? -1e30f : v;
                }
            }
            __syncthreads();   // all K reads done before P overwrites KPs

            // online softmax (row stats reduced over the 16 threads of a row
            // group, which are 16 consecutive lanes -> shfl_xor 8/4/2/1)
            #pragma unroll
            for (int i = 0; i < 4; i++) {
                float tmax = fmaxf(fmaxf(s[i][0], s[i][1]),
                                   fmaxf(s[i][2], s[i][3]));
                #pragma unroll
                for (int off = 8; off >= 1; off >>= 1)
                    tmax = fmaxf(tmax, __shfl_xor_sync(0xffffffffu, tmax, off));
                float mnew = fmaxf(m_i[i], tmax);
                float alpha = fast_exp(m_i[i] - mnew);
                float rsum = 0.f;
                #pragma unroll
                for (int j = 0; j < 4; j++) {
                    float p = fast_exp(s[i][j] - mnew);
                    s[i][j] = p;
                    rsum += p;
                }
                #pragma unroll
                for (int off = 8; off >= 1; off >>= 1)
                    rsum += __shfl_xor_sync(0xffffffffu, rsum, off);
                l_i[i] = l_i[i] * alpha + rsum;
                m_i[i] = mnew;
                #pragma unroll
                for (int j = 0; j < 4; j++) O[i][j] *= alpha;
            }

            // store P as [c][r], row-group XOR-swizzled (g = tr ^ c_group) to
            // break the stride-256B same-bank pattern (16-way -> 4-way)
            #pragma unroll
            for (int j = 0; j < 4; j++) {
                int c = tc * 4 + j;
                int g = (tr ^ tc) & 15;    // c>>2 == tc
                #pragma unroll
                for (int i = 0; i < 4; i++)
                    KPs[c][g * 4 + i] = s[i][j];
            }
            __syncthreads();

            // O += P V (4x4 per thread)
            #pragma unroll 8
            for (int c = 0; c < 64; c++) {
                float pv[4], vv[4];
                int g = (tr ^ (c >> 2)) & 15;
                *(float4*)pv = *(const float4*)&KPs[c][g * 4];
                *(float4*)vv = *(const float4*)&Vs[c][tc * 4];
                #pragma unroll
                for (int i = 0; i < 4; i++)
                    #pragma unroll
                    for (int j = 0; j < 4; j++)
                        O[i][j] = fmaf(pv[i], vv[j], O[i][j]);
            }
        }

        // epilogue: normalize, write g_y in (b,t,h,d)
        const int b = bh >> 4;
        #pragma unroll
        for (int i = 0; i < 4; i++) {
            int qi = qt * 64 + tr * 4 + i;
            float inv = 1.0f / l_i[i];
            float4 o;
            o.x = O[i][0] * inv; o.y = O[i][1] * inv;
            o.z = O[i][2] * inv; o.w = O[i][3] * inv;
            *(float4*)(g_y + ((size_t)((b*TT + qi)*HH + h)) * HD + tc * 4) = o;
        }
    }
}

// ---------------------------------------------------------------------------
extern "C" void kernel_launch(void* const* d_in, const int* in_sizes, int n_in,
                              void* d_out, int out_size) {
    const float* x_norm   = (const float*)d_in[0];
    const float* xt       = (const float*)d_in[1];
    const float* qk_w     = (const float*)d_in[2];
    const float* qk_b     = (const float*)d_in[3];
    const float* v_fact   = (const float*)d_in[4];
    const float* out_fact = (const float*)d_in[5];
    float* out = (float*)d_out;

    qk_proj_kernel<<<dim3(DD*2/128, BB*TT/128), 256>>>(x_norm, qk_w, qk_b);
    mix_kernel<<<BB*TT, 256>>>(xt, v_fact, nullptr, 0);
    attn_kernel<<<dim3(16, BB*HH), 256>>>();
    mix_kernel<<<BB*TT, 256>>>(nullptr, out_fact, out, 1);
}